// round 8
// baseline (speedup 1.0000x reference)
#include <cuda_runtime.h>
#include <cuda_bf16.h>
#include <math.h>

#define NN 4096
#define TT 48
#define MAXNZ 128
#define SZH (NN*64)
#define GRID 128
#define RPB 32          // rows per block

// ---------------- device scratch (static, no allocation) ----------------
__device__ float g_dinv[NN];
__device__ int   g_cnt[NN];
__device__ int   g_cols[NN*MAXNZ];   // zero-init beyond cnt -> safe padded reads
__device__ float g_vals[NN*MAXNZ];   // zero-init beyond cnt -> products vanish
__device__ float g_Xall[NN*96];
__device__ float g_AX[NN*96];
__device__ float g_h0[2*SZH];
__device__ float g_h1[2*SZH];
__device__ float g_c0[SZH];
__device__ float g_c1[SZH];
__device__ float g_b0[256];
__device__ float g_b1[256];
__device__ float g_WX[4*256];                    // [gcWi0 rows 0,1 ; liWi0 rows 0,1]
__device__ __align__(16) unsigned g_Wf0[32768];  // layer0 W frags (K=128)
__device__ __align__(16) unsigned g_Wf1[65536];  // layer1 W frags (K=256)
__device__ unsigned g_bar;                       // global barrier counter

__device__ __forceinline__ float sigf(float x) { return 1.0f / (1.0f + expf(-x)); }

// bf16 mma: D += A(16x16) * B(16x8), fp32 accum
#define MMA_BF16(C, A, b0, b1) \
    asm volatile("mma.sync.aligned.m16n8k16.row.col.f32.bf16.bf16.f32 " \
        "{%0,%1,%2,%3}, {%4,%5,%6,%7}, {%8,%9}, {%0,%1,%2,%3};" \
        : "+f"(C[0]), "+f"(C[1]), "+f"(C[2]), "+f"(C[3]) \
        : "r"(A[0]), "r"(A[1]), "r"(A[2]), "r"(A[3]), "r"(b0), "r"(b1))

__device__ __forceinline__ void cp_async16(void* s, const void* g) {
    unsigned sa = (unsigned)__cvta_generic_to_shared(s);
    asm volatile("cp.async.ca.shared.global [%0], [%1], 16;" :: "r"(sa), "l"(g));
}
__device__ __forceinline__ void cp_commit() {
    asm volatile("cp.async.commit_group;");
}
template<int Nq> __device__ __forceinline__ void cp_wait() {
    asm volatile("cp.async.wait_group %0;" :: "n"(Nq));
}

// pack float2 -> bf16 hi-pair + lo-pair (residual), store as u32 each
__device__ __forceinline__ void store_hilo(__nv_bfloat16* bhi, __nv_bfloat16* blo,
                                           int off, float2 v) {
    const __nv_bfloat16 hx = __float2bfloat16(v.x), hy = __float2bfloat16(v.y);
    const float rx = v.x - __bfloat162float(hx);
    const float ry = v.y - __bfloat162float(hy);
    const unsigned uh = (unsigned)__bfloat16_as_ushort(hx)
                      | ((unsigned)__bfloat16_as_ushort(hy) << 16);
    const unsigned ul = (unsigned)__bfloat16_as_ushort(__float2bfloat16(rx))
                      | ((unsigned)__bfloat16_as_ushort(__float2bfloat16(ry)) << 16);
    *(unsigned*)(bhi + off) = uh;
    *(unsigned*)(blo + off) = ul;
}

// software global barrier: monotone counter within one launch; reset by setup
__device__ __forceinline__ void gbar(unsigned target) {
    __threadfence();
    __syncthreads();
    if (threadIdx.x == 0) {
        atomicAdd(&g_bar, 1u);
        while (atomicAdd(&g_bar, 0u) < target) __nanosleep(64);
        __threadfence();
    }
    __syncthreads();
}

// ---------------- setup kernels ----------------

__global__ void deg_kernel(const float* __restrict__ adj) {
    __shared__ float red[256];
    const int r = blockIdx.x;
    float s = 0.0f;
    for (int c = threadIdx.x; c < NN; c += 256) s += adj[(long)r*NN + c];
    red[threadIdx.x] = s;
    __syncthreads();
    for (int o = 128; o > 0; o >>= 1) {
        if (threadIdx.x < o) red[threadIdx.x] += red[threadIdx.x + o];
        __syncthreads();
    }
    if (threadIdx.x == 0) g_dinv[r] = 1.0f / sqrtf(red[0] + 1.0f);
}

__global__ void ell_kernel(const float* __restrict__ adj) {
    const int lane = threadIdx.x & 31;
    const int r = blockIdx.x * 8 + (threadIdx.x >> 5);
    const float dr = g_dinv[r];
    int base = 0;
    for (int c0 = 0; c0 < NN; c0 += 32) {
        const int c = c0 + lane;
        float a = adj[(long)r*NN + c];
        if (c == r) a += 1.0f;
        const unsigned m = __ballot_sync(0xffffffffu, a != 0.0f);
        if (a != 0.0f) {
            const int pos = base + __popc(m & ((1u << lane) - 1u));
            if (pos < MAXNZ) {
                g_cols[r*MAXNZ + pos] = c;
                g_vals[r*MAXNZ + pos] = a * dr * g_dinv[c];
            }
        }
        base += __popc(m);
    }
    if (lane == 0) g_cnt[r] = (base < MAXNZ) ? base : MAXNZ;
}

// merged setup: Xall transpose + state zero + W frags + biases + barrier reset
__global__ void setup_kernel(
    const float* __restrict__ x,
    const float* __restrict__ gcWh0, const float* __restrict__ liWh0,
    const float* __restrict__ gcWi1, const float* __restrict__ liWi1,
    const float* __restrict__ gcWh1, const float* __restrict__ liWh1,
    const float* __restrict__ gcWi0, const float* __restrict__ liWi0,
    const float* __restrict__ gcbi0, const float* __restrict__ gcbh0,
    const float* __restrict__ libi0, const float* __restrict__ libh0,
    const float* __restrict__ gcbi1, const float* __restrict__ gcbh1,
    const float* __restrict__ libi1, const float* __restrict__ libh1)
{
    const int idx = blockIdx.x * 256 + threadIdx.x;   // < NN*96
    {   // Xall + zero
        const int n = idx / 96;
        const int q = idx - n * 96;
        const int t = q >> 1, i = q & 1;
        g_Xall[idx] = x[t * (NN*2) + n*2 + i];
        if (idx < SZH) {
            g_h0[idx] = 0.f; g_h0[SZH + idx] = 0.f;
            g_h1[idx] = 0.f; g_h1[SZH + idx] = 0.f;
            g_c0[idx] = 0.f; g_c1[idx] = 0.f;
        }
    }
    if (idx < 98304) {   // W fragments
        const int L = (idx >= 32768);
        const int j = L ? idx - 32768 : idx;
        const int lane = j & 31, hl = (j >> 5) & 1, b = (j >> 6) & 1;
        const int nt = (j >> 7) & 31, ks = j >> 12;
        const int g = lane >> 2, tig = lane & 3;
        const int k0 = ks*16 + b*8 + 2*tig;
        const int n  = nt*8 + g;
        unsigned short h2[2];
        #pragma unroll
        for (int e = 0; e < 2; e++) {
            const int k = k0 + e;
            const float* src;
            if (!L) src = (k < 64) ? (gcWh0 + k*256) : (liWh0 + (k-64)*256);
            else {
                const int q = k >> 6;
                src = (q == 0) ? (gcWi1 + k*256)
                    : (q == 1) ? (liWi1 + (k-64)*256)
                    : (q == 2) ? (gcWh1 + (k-128)*256)
                               : (liWh1 + (k-192)*256);
            }
            const float w = src[n];
            __nv_bfloat16 bh = __float2bfloat16(w);
            if (hl) bh = __float2bfloat16(w - __bfloat162float(bh));
            h2[e] = __bfloat16_as_ushort(bh);
        }
        const unsigned val = (unsigned)h2[0] | ((unsigned)h2[1] << 16);
        if (L) g_Wf1[j] = val; else g_Wf0[j] = val;
    }
    if (blockIdx.x == 0) {
        const int c = threadIdx.x;
        g_b0[c] = gcbi0[c] + gcbh0[c] + libi0[c] + libh0[c];
        g_b1[c] = gcbi1[c] + gcbh1[c] + libi1[c] + libh1[c];
        g_WX[c]       = gcWi0[c];
        g_WX[256 + c] = gcWi0[256 + c];
        g_WX[512 + c] = liWi0[c];
        g_WX[768 + c] = liWi0[256 + c];
        if (c == 0) g_bar = 0u;     // reset global barrier each launch
    }
}

// ---------------- persistent cell phase ----------------
// smem layout (fixed): s_src 4 slots x 2 halves x (32*72) bf16 = 36864 B,
// s_w ring 2 x 16 KB = 32768 B, s_comb 32x256 f32 = 32768 B. Total 102400 B.
// NSRC==1: layer0 (slots 0=Ah,1=h, K=128). NSRC==2: layer1 (+slots 2=Ah',3=h').
// Cross-block h reads use __ldcg (L1 not coherent inside a persistent kernel).
template<int NSRC>
__device__ __forceinline__ void cell_phase(
    char* smem, int r0, int t,
    const float2* __restrict__ hA2, const float2* __restrict__ hB2,
    float* __restrict__ hout, float* __restrict__ cst,
    const unsigned* __restrict__ WF, const float* __restrict__ btot)
{
    constexpr int NCH  = NSRC * 8;       // 16KB W chunks
    constexpr int HALF = RPB * 72;
    __nv_bfloat16* s_src = (__nv_bfloat16*)smem;
    unsigned*      s_w   = (unsigned*)(smem + 36864);
    float*         s_comb= (float*)(smem + 36864 + 32768);

    const int tid = threadIdx.x, lane = tid & 31, warp = tid >> 5;

    auto issue_chunk = [&](int c) {
        const float4* gsrc = (const float4*)(WF + c*4096);
        float4* dst = (float4*)(s_w + (c & 1)*4096);
        cp_async16(dst + tid,       gsrc + tid);
        cp_async16(dst + tid + 512, gsrc + tid + 512);
        cp_commit();
    };
    issue_chunk(0);
    issue_chunk(1);

    // ---- stage h slots (slot1 = hA rows, slot3 = hB rows; own rows) ----
    for (int i = tid; i < RPB*32; i += 512) {
        const int n = i >> 5, l2 = i & 31;
        store_hilo(s_src + 2*HALF, s_src + 3*HALF, n*72 + 2*l2,
                   hA2[(r0+n)*32 + l2]);
        if (NSRC == 2)
            store_hilo(s_src + 6*HALF, s_src + 7*HALF, n*72 + 2*l2,
                       hB2[(r0+n)*32 + l2]);
    }

    // ---- SpMM gather: 2 rows per warp, interleaved for MLP ----
    {
        const int rA = r0 + warp, rB = r0 + warp + 16;
        const int cnA = (g_cnt[rA] + 3) & ~3;
        const int cnB = (g_cnt[rB] + 3) & ~3;
        const int kmax = cnA > cnB ? cnA : cnB;
        const int*   cpA = g_cols + rA*MAXNZ;
        const float* vpA = g_vals + rA*MAXNZ;
        const int*   cpB = g_cols + rB*MAXNZ;
        const float* vpB = g_vals + rB*MAXNZ;
        float2 aA0 = {0.f,0.f}, aA1 = {0.f,0.f};
        float2 aB0 = {0.f,0.f}, aB1 = {0.f,0.f};
        #pragma unroll 1
        for (int k = 0; k < kmax; k += 4) {
            const int4   cA = *(const int4*)(cpA + k);
            const float4 vA = *(const float4*)(vpA + k);
            const int4   cB = *(const int4*)(cpB + k);
            const float4 vB = *(const float4*)(vpB + k);
            const int   ca[4] = {cA.x, cA.y, cA.z, cA.w};
            const float va[4] = {vA.x, vA.y, vA.z, vA.w};
            const int   cb[4] = {cB.x, cB.y, cB.z, cB.w};
            const float vb[4] = {vB.x, vB.y, vB.z, vB.w};
            #pragma unroll
            for (int u = 0; u < 4; u++) {
                const float2 p = __ldcg(hA2 + ca[u]*32 + lane);
                aA0.x += va[u]*p.x; aA0.y += va[u]*p.y;
                const float2 r = __ldcg(hA2 + cb[u]*32 + lane);
                aB0.x += vb[u]*r.x; aB0.y += vb[u]*r.y;
                if (NSRC == 2) {
                    const float2 q = __ldcg(hB2 + ca[u]*32 + lane);
                    aA1.x += va[u]*q.x; aA1.y += va[u]*q.y;
                    const float2 s = __ldcg(hB2 + cb[u]*32 + lane);
                    aB1.x += vb[u]*s.x; aB1.y += vb[u]*s.y;
                }
            }
        }
        store_hilo(s_src,          s_src + HALF,   warp*72 + 2*lane, aA0);
        store_hilo(s_src,          s_src + HALF,   (warp+16)*72 + 2*lane, aB0);
        if (NSRC == 2) {
            store_hilo(s_src + 4*HALF, s_src + 5*HALF, warp*72 + 2*lane, aA1);
            store_hilo(s_src + 4*HALF, s_src + 5*HALF, (warp+16)*72 + 2*lane, aB1);
        }
    }
    __syncthreads();

    // ---- tensor-core GEMM over NCH chunks (2-deep cp.async ring) ----
    const int g = lane >> 2, tig = lane & 3;
    const int mt = warp >> 3, ng = warp & 7;
    float acc[4][4];
    #pragma unroll
    for (int nt = 0; nt < 4; nt++) {
        const int col = (ng*4 + nt)*8 + 2*tig;
        const float b0v = btot[col], b1v = btot[col+1];
        acc[nt][0] = b0v; acc[nt][1] = b1v; acc[nt][2] = b0v; acc[nt][3] = b1v;
    }

    #pragma unroll 1
    for (int c = 0; c < NCH; c++) {
        if (c + 1 == NCH) cp_wait<0>(); else cp_wait<1>();
        __syncthreads();                          // chunk c resident
        const int slot = c >> 2, ks = c & 3;
        const __nv_bfloat16* ah = s_src + (slot*2+0)*HALF;
        const __nv_bfloat16* al = s_src + (slot*2+1)*HALF;
        unsigned Ah[4], Al[4];
        const int ab = (mt*16 + g)*72 + ks*16 + 2*tig;
        Ah[0] = *(const unsigned*)(ah + ab);
        Ah[1] = *(const unsigned*)(ah + ab + 8*72);
        Ah[2] = *(const unsigned*)(ah + ab + 8);
        Ah[3] = *(const unsigned*)(ah + ab + 8*72 + 8);
        Al[0] = *(const unsigned*)(al + ab);
        Al[1] = *(const unsigned*)(al + ab + 8*72);
        Al[2] = *(const unsigned*)(al + ab + 8);
        Al[3] = *(const unsigned*)(al + ab + 8*72 + 8);
        const unsigned* wp = s_w + (c & 1)*4096 + ng*512 + lane;
        #pragma unroll
        for (int nt = 0; nt < 4; nt++) {
            const unsigned b0h = wp[nt*128];
            const unsigned b1h = wp[nt*128 + 64];
            const unsigned b0l = wp[nt*128 + 32];
            const unsigned b1l = wp[nt*128 + 96];
            MMA_BF16(acc[nt], Ah, b0h, b1h);
            MMA_BF16(acc[nt], Ah, b0l, b1l);
            MMA_BF16(acc[nt], Al, b0h, b1h);
        }
        __syncthreads();                          // chunk c reads done
        if (c + 2 < NCH) issue_chunk(c + 2);
    }

    if (NSRC == 1) {   // layer0 rank-2 x terms: (A x_t)@gcWi0 + x_t@liWi0
        const int rA = r0 + mt*16 + g, rB = rA + 8;
        float sA[4], sB[4];
        sA[0] = g_AX  [rA*96 + 2*t]; sA[1] = g_AX  [rA*96 + 2*t + 1];
        sA[2] = g_Xall[rA*96 + 2*t]; sA[3] = g_Xall[rA*96 + 2*t + 1];
        sB[0] = g_AX  [rB*96 + 2*t]; sB[1] = g_AX  [rB*96 + 2*t + 1];
        sB[2] = g_Xall[rB*96 + 2*t]; sB[3] = g_Xall[rB*96 + 2*t + 1];
        #pragma unroll
        for (int nt = 0; nt < 4; nt++) {
            const int col = (ng*4 + nt)*8 + 2*tig;
            #pragma unroll
            for (int jx = 0; jx < 4; jx++) {
                const float w0 = g_WX[jx*256 + col], w1 = g_WX[jx*256 + col + 1];
                acc[nt][0] += sA[jx]*w0; acc[nt][1] += sA[jx]*w1;
                acc[nt][2] += sB[jx]*w0; acc[nt][3] += sB[jx]*w1;
            }
        }
    }

    // ---- comb -> smem, gates ----
    #pragma unroll
    for (int nt = 0; nt < 4; nt++) {
        const int col = (ng*4 + nt)*8 + 2*tig;
        *(float2*)(s_comb + (mt*16 + g)*256 + col)     = make_float2(acc[nt][0], acc[nt][1]);
        *(float2*)(s_comb + (mt*16 + g + 8)*256 + col) = make_float2(acc[nt][2], acc[nt][3]);
    }
    __syncthreads();
    for (int i = tid; i < RPB*64; i += 512) {
        const int n = i >> 6, hc = i & 63;
        const float ig = s_comb[n*256 + hc];
        const float fg = s_comb[n*256 + 64  + hc];
        const float og = s_comb[n*256 + 128 + hc];
        const float gg = s_comb[n*256 + 192 + hc];
        const int gi = (r0 + n)*64 + hc;
        const float cold = cst[gi];
        const float cnew = sigf(fg)*cold + sigf(ig)*tanhf(gg);
        cst[gi]  = cnew;
        hout[gi] = sigf(og)*tanhf(cnew);
    }
}

// ---------------- persistent kernel: all 48 steps, 2 global barriers/step ----
__global__ void __launch_bounds__(512, 1) persist_kernel()
{
    extern __shared__ char smem[];
    const int tid = threadIdx.x, lane = tid & 31, warp = tid >> 5;
    const int r0 = blockIdx.x * RPB;

    // prologue: AX = A @ Xall for own rows (block-private; no barrier needed)
    for (int rr = warp; rr < RPB; rr += 16) {
        const int r = r0 + rr;
        const int cn = (g_cnt[r] + 3) & ~3;
        const int*   cp = g_cols + r*MAXNZ;
        const float* vp = g_vals + r*MAXNZ;
        float a0 = 0.f, a1 = 0.f, a2 = 0.f;
        #pragma unroll 1
        for (int k = 0; k < cn; k += 4) {
            const int4   c4 = *(const int4*)(cp + k);
            const float4 v4 = *(const float4*)(vp + k);
            const int   cc[4] = {c4.x, c4.y, c4.z, c4.w};
            const float vv[4] = {v4.x, v4.y, v4.z, v4.w};
            #pragma unroll
            for (int u = 0; u < 4; u++) {
                a0 += vv[u] * g_Xall[cc[u]*96 + lane];
                a1 += vv[u] * g_Xall[cc[u]*96 + lane + 32];
                a2 += vv[u] * g_Xall[cc[u]*96 + lane + 64];
            }
        }
        g_AX[r*96 + lane]      = a0;
        g_AX[r*96 + lane + 32] = a1;
        g_AX[r*96 + lane + 64] = a2;
    }
    __syncthreads();

    unsigned target = 0;
    for (int t = 0; t < TT; t++) {
        const int pi = t & 1, po = pi ^ 1;
        cell_phase<1>(smem, r0, t,
                      (const float2*)(g_h0 + pi*SZH), (const float2*)0,
                      g_h0 + po*SZH, g_c0, g_Wf0, g_b0);
        target += GRID; gbar(target);
        cell_phase<2>(smem, r0, t,
                      (const float2*)(g_h0 + po*SZH), (const float2*)(g_h1 + pi*SZH),
                      g_h1 + po*SZH, g_c1, g_Wf1, g_b1);
        if (t < TT - 1) { target += GRID; gbar(target); }
    }
}

// out[n,p] = h1_final[n,:] @ outW + outb
__global__ void outproj_kernel(const float* __restrict__ outW,
                               const float* __restrict__ outb,
                               float* __restrict__ out) {
    const int idx = blockIdx.x*blockDim.x + threadIdx.x;
    if (idx >= NN*12) return;
    const int n = idx / 12, p = idx - n*12;
    const float* h = g_h1 + n*64;    // final ping index 0 after t=47
    float s = outb[p];
    #pragma unroll
    for (int k = 0; k < 64; k++) s += h[k] * outW[k*12 + p];
    out[idx] = s;
}

// ---------------- launch ----------------
extern "C" void kernel_launch(void* const* d_in, const int* in_sizes, int n_in,
                              void* d_out, int out_size) {
    (void)in_sizes; (void)n_in; (void)out_size;
    const float* x     = (const float*)d_in[0];
    const float* adj   = (const float*)d_in[1];
    const float* gcWi0 = (const float*)d_in[2];
    const float* gcbi0 = (const float*)d_in[3];
    const float* gcWh0 = (const float*)d_in[4];
    const float* gcbh0 = (const float*)d_in[5];
    const float* liWi0 = (const float*)d_in[6];
    const float* libi0 = (const float*)d_in[7];
    const float* liWh0 = (const float*)d_in[8];
    const float* libh0 = (const float*)d_in[9];
    const float* gcWi1 = (const float*)d_in[10];
    const float* gcbi1 = (const float*)d_in[11];
    const float* gcWh1 = (const float*)d_in[12];
    const float* gcbh1 = (const float*)d_in[13];
    const float* liWi1 = (const float*)d_in[14];
    const float* libi1 = (const float*)d_in[15];
    const float* liWh1 = (const float*)d_in[16];
    const float* libh1 = (const float*)d_in[17];
    const float* outW  = (const float*)d_in[18];
    const float* outb  = (const float*)d_in[19];
    float* out = (float*)d_out;

    const int SMEM = 36864 + 32768 + 32768;   // 102400
    cudaFuncSetAttribute(persist_kernel,
                         cudaFuncAttributeMaxDynamicSharedMemorySize, SMEM);

    deg_kernel  <<<NN, 256>>>(adj);
    ell_kernel  <<<NN/8, 256>>>(adj);
    setup_kernel<<<(NN*96)/256, 256>>>(x, gcWh0, liWh0, gcWi1, liWi1, gcWh1, liWh1,
                                       gcWi0, liWi0,
                                       gcbi0, gcbh0, libi0, libh0,
                                       gcbi1, gcbh1, libi1, libh1);
    persist_kernel<<<GRID, 512, SMEM>>>();
    outproj_kernel<<<(NN*12 + 255)/256, 256>>>(outW, outb, out);
}

// round 9
// speedup vs baseline: 1.3735x; 1.3735x over previous
#include <cuda_runtime.h>
#include <cuda_bf16.h>
#include <math.h>

#define NN 4096
#define TT 48
#define MAXNZ 128
#define SZH (NN*64)
#define RPB 32          // rows per block
#define GRID (NN/RPB)   // 128

// ---------------- device scratch (static, no allocation) ----------------
__device__ float g_dinv[NN];
__device__ int   g_cnt[NN];
__device__ int   g_cols[NN*MAXNZ];   // zero beyond cnt -> safe padded reads
__device__ float g_vals[NN*MAXNZ];   // zero beyond cnt -> products vanish
__device__ float g_Xall[NN*96];
__device__ float g_AX[NN*96];
__device__ float g_h0[2*SZH];
__device__ float g_h1[2*SZH];
__device__ float g_c0[SZH];
__device__ float g_c1[SZH];
__device__ float g_b0[256];
__device__ float g_b1[256];
__device__ float g_WX[4*256];                    // [gcWi0 rows 0,1 ; liWi0 rows 0,1]
__device__ __align__(16) unsigned g_Wf0[32768];  // layer0 W frags (K=128)
__device__ __align__(16) unsigned g_Wf1[65536];  // layer1 W frags (K=256)

__device__ __forceinline__ float sigf(float x) { return 1.0f / (1.0f + expf(-x)); }

// bf16 mma: D += A(16x16) * B(16x8), fp32 accum
#define MMA_BF16(C, A, b0, b1) \
    asm volatile("mma.sync.aligned.m16n8k16.row.col.f32.bf16.bf16.f32 " \
        "{%0,%1,%2,%3}, {%4,%5,%6,%7}, {%8,%9}, {%0,%1,%2,%3};" \
        : "+f"(C[0]), "+f"(C[1]), "+f"(C[2]), "+f"(C[3]) \
        : "r"(A[0]), "r"(A[1]), "r"(A[2]), "r"(A[3]), "r"(b0), "r"(b1))

__device__ __forceinline__ void cp_async16(void* s, const void* g) {
    unsigned sa = (unsigned)__cvta_generic_to_shared(s);
    asm volatile("cp.async.ca.shared.global [%0], [%1], 16;" :: "r"(sa), "l"(g));
}
__device__ __forceinline__ void cp_commit() {
    asm volatile("cp.async.commit_group;");
}
template<int Nq> __device__ __forceinline__ void cp_wait() {
    asm volatile("cp.async.wait_group %0;" :: "n"(Nq));
}

// pack float2 -> bf16 hi-pair + lo-pair (residual), store as u32 each
__device__ __forceinline__ void store_hilo(__nv_bfloat16* bhi, __nv_bfloat16* blo,
                                           int off, float2 v) {
    const __nv_bfloat16 hx = __float2bfloat16(v.x), hy = __float2bfloat16(v.y);
    const float rx = v.x - __bfloat162float(hx);
    const float ry = v.y - __bfloat162float(hy);
    const unsigned uh = (unsigned)__bfloat16_as_ushort(hx)
                      | ((unsigned)__bfloat16_as_ushort(hy) << 16);
    const unsigned ul = (unsigned)__bfloat16_as_ushort(__float2bfloat16(rx))
                      | ((unsigned)__bfloat16_as_ushort(__float2bfloat16(ry)) << 16);
    *(unsigned*)(bhi + off) = uh;
    *(unsigned*)(blo + off) = ul;
}

// ---------------- setup kernels ----------------

__global__ void deg_kernel(const float* __restrict__ adj) {
    __shared__ float red[256];
    const int r = blockIdx.x;
    float s = 0.0f;
    for (int c = threadIdx.x; c < NN; c += 256) s += adj[(long)r*NN + c];
    red[threadIdx.x] = s;
    __syncthreads();
    for (int o = 128; o > 0; o >>= 1) {
        if (threadIdx.x < o) red[threadIdx.x] += red[threadIdx.x + o];
        __syncthreads();
    }
    if (threadIdx.x == 0) g_dinv[r] = 1.0f / sqrtf(red[0] + 1.0f);
}

__global__ void ell_kernel(const float* __restrict__ adj) {
    const int lane = threadIdx.x & 31;
    const int r = blockIdx.x * 8 + (threadIdx.x >> 5);
    const float dr = g_dinv[r];
    int base = 0;
    for (int c0 = 0; c0 < NN; c0 += 32) {
        const int c = c0 + lane;
        float a = adj[(long)r*NN + c];
        if (c == r) a += 1.0f;
        const unsigned m = __ballot_sync(0xffffffffu, a != 0.0f);
        if (a != 0.0f) {
            const int pos = base + __popc(m & ((1u << lane) - 1u));
            if (pos < MAXNZ) {
                g_cols[r*MAXNZ + pos] = c;
                g_vals[r*MAXNZ + pos] = a * dr * g_dinv[c];
            }
        }
        base += __popc(m);
    }
    if (lane == 0) g_cnt[r] = (base < MAXNZ) ? base : MAXNZ;
}

// merged: Xall transpose + state zeroing
__global__ void xallzero_kernel(const float* __restrict__ x) {
    const int idx = blockIdx.x * 256 + threadIdx.x;   // < NN*96
    const int n = idx / 96;
    const int q = idx - n * 96;
    const int t = q >> 1, i = q & 1;
    g_Xall[idx] = x[t * (NN*2) + n*2 + i];
    if (idx < SZH) {
        g_h0[idx] = 0.f; g_h0[SZH + idx] = 0.f;
        g_h1[idx] = 0.f; g_h1[SZH + idx] = 0.f;
        g_c0[idx] = 0.f; g_c1[idx] = 0.f;
    }
}

__global__ void spmm96_kernel() {
    const int lane = threadIdx.x & 31;
    const int r = blockIdx.x * 8 + (threadIdx.x >> 5);
    const int cn = (g_cnt[r] + 3) & ~3;
    const int*   cp = g_cols + r*MAXNZ;
    const float* vp = g_vals + r*MAXNZ;
    float a0 = 0.f, a1 = 0.f, a2 = 0.f;
    #pragma unroll 1
    for (int k = 0; k < cn; k += 4) {
        const int4   c4 = *(const int4*)(cp + k);
        const float4 v4 = *(const float4*)(vp + k);
        const int   cc[4] = {c4.x, c4.y, c4.z, c4.w};
        const float vv[4] = {v4.x, v4.y, v4.z, v4.w};
        #pragma unroll
        for (int u = 0; u < 4; u++) {
            a0 += vv[u] * g_Xall[cc[u]*96 + lane];
            a1 += vv[u] * g_Xall[cc[u]*96 + lane + 32];
            a2 += vv[u] * g_Xall[cc[u]*96 + lane + 64];
        }
    }
    g_AX[r*96 + lane]      = a0;
    g_AX[r*96 + lane + 32] = a1;
    g_AX[r*96 + lane + 64] = a2;
}

// merged: W fragment build + bias/WX prep (block 0)
// frag layout within layer: (((ks*32 + nt)*2 + b)*2 + hl)*32 + lane
// k = ks*16 + b*8 + 2*tig (+1), n = nt*8 + g  (lane = g*4 + tig)
__global__ void wfragbias_kernel(
    const float* __restrict__ gcWh0, const float* __restrict__ liWh0,
    const float* __restrict__ gcWi1, const float* __restrict__ liWi1,
    const float* __restrict__ gcWh1, const float* __restrict__ liWh1,
    const float* __restrict__ gcWi0, const float* __restrict__ liWi0,
    const float* __restrict__ gcbi0, const float* __restrict__ gcbh0,
    const float* __restrict__ libi0, const float* __restrict__ libh0,
    const float* __restrict__ gcbi1, const float* __restrict__ gcbh1,
    const float* __restrict__ libi1, const float* __restrict__ libh1)
{
    const int idx = blockIdx.x * 256 + threadIdx.x;    // < 98304
    if (idx < 98304) {
        const int L = (idx >= 32768);
        const int j = L ? idx - 32768 : idx;
        const int lane = j & 31, hl = (j >> 5) & 1, b = (j >> 6) & 1;
        const int nt = (j >> 7) & 31, ks = j >> 12;
        const int g = lane >> 2, tig = lane & 3;
        const int k0 = ks*16 + b*8 + 2*tig;
        const int n  = nt*8 + g;
        unsigned short h2[2];
        #pragma unroll
        for (int e = 0; e < 2; e++) {
            const int k = k0 + e;
            const float* src;
            if (!L) src = (k < 64) ? (gcWh0 + k*256) : (liWh0 + (k-64)*256);
            else {
                const int q = k >> 6;
                src = (q == 0) ? (gcWi1 + k*256)
                    : (q == 1) ? (liWi1 + (k-64)*256)
                    : (q == 2) ? (gcWh1 + (k-128)*256)
                               : (liWh1 + (k-192)*256);
            }
            const float w = src[n];
            __nv_bfloat16 bh = __float2bfloat16(w);
            if (hl) bh = __float2bfloat16(w - __bfloat162float(bh));
            h2[e] = __bfloat16_as_ushort(bh);
        }
        const unsigned val = (unsigned)h2[0] | ((unsigned)h2[1] << 16);
        if (L) g_Wf1[j] = val; else g_Wf0[j] = val;
    }
    if (blockIdx.x == 0) {
        const int c = threadIdx.x;
        g_b0[c] = gcbi0[c] + gcbh0[c] + libi0[c] + libh0[c];
        g_b1[c] = gcbi1[c] + gcbh1[c] + libi1[c] + libh1[c];
        g_WX[c]       = gcWi0[c];
        g_WX[256 + c] = gcWi0[256 + c];
        g_WX[512 + c] = liWi0[c];
        g_WX[768 + c] = liWi0[256 + c];
    }
}

// ---------------- fused cell kernel (32 rows/CTA, 512 threads) ----------------
// smem: s_src 4 slots x 2 halves x (32*72) bf16 = 36864 B,
//       s_w ring 2 x 16 KB = 32768 B, s_comb 32x256 f32 = 32768 B -> 102400 B.
// Phase 1: cp.async W prefetch; stage h bf16 hi/lo; SpMM gather (2 rows/warp
//          interleaved, L1-cached float2 loads, zero-padded ELL).
// Phase 2: comb = src @ Wcat via mma.sync bf16 x3; 2-deep cp.async W ring.
// Phase 3: LSTM gates.
template<int LAYER>
__global__ void __launch_bounds__(512, 1) cell_kernel(int pi, int t)
{
    constexpr int NSRC = (LAYER == 0) ? 1 : 2;
    constexpr int NCH  = NSRC * 8;       // 16KB W chunks
    constexpr int HALF = RPB * 72;
    extern __shared__ char smem[];
    __nv_bfloat16* s_src = (__nv_bfloat16*)smem;
    unsigned*      s_w   = (unsigned*)(smem + 36864);
    float*         s_comb= (float*)(smem + 36864 + 32768);

    const int po = pi ^ 1;
    const float* __restrict__ hA   = (LAYER == 0) ? (g_h0 + pi*SZH) : (g_h0 + po*SZH);
    const float* __restrict__ hB   = g_h1 + pi*SZH;
    float*       __restrict__ hout = (LAYER == 0) ? (g_h0 + po*SZH) : (g_h1 + po*SZH);
    float*       __restrict__ cst  = (LAYER == 0) ? g_c0 : g_c1;
    const float* __restrict__ btot = (LAYER == 0) ? g_b0 : g_b1;
    const unsigned* __restrict__ WF = (LAYER == 0) ? g_Wf0 : g_Wf1;
    const float2* __restrict__ hA2 = (const float2*)hA;
    const float2* __restrict__ hB2 = (const float2*)hB;

    const int tid = threadIdx.x, lane = tid & 31, warp = tid >> 5;
    const int r0 = blockIdx.x * RPB;

    auto issue_chunk = [&](int c) {
        const float4* gsrc = (const float4*)(WF + c*4096);
        float4* dst = (float4*)(s_w + (c & 1)*4096);
        cp_async16(dst + tid,       gsrc + tid);
        cp_async16(dst + tid + 512, gsrc + tid + 512);
        cp_commit();
    };
    issue_chunk(0);
    issue_chunk(1);

    // ---- stage h slots (slot1 = hA rows, slot3 = hB rows; own rows) ----
    for (int i = tid; i < RPB*32; i += 512) {
        const int n = i >> 5, l2 = i & 31;
        store_hilo(s_src + 2*HALF, s_src + 3*HALF, n*72 + 2*l2,
                   hA2[(r0+n)*32 + l2]);
        if (NSRC == 2)
            store_hilo(s_src + 6*HALF, s_src + 7*HALF, n*72 + 2*l2,
                       hB2[(r0+n)*32 + l2]);
    }

    // ---- SpMM gather: 2 rows per warp, interleaved for MLP ----
    {
        const int rA = r0 + warp, rB = r0 + warp + 16;
        const int cnA = (g_cnt[rA] + 3) & ~3;
        const int cnB = (g_cnt[rB] + 3) & ~3;
        const int kmax = cnA > cnB ? cnA : cnB;
        const int*   cpA = g_cols + rA*MAXNZ;
        const float* vpA = g_vals + rA*MAXNZ;
        const int*   cpB = g_cols + rB*MAXNZ;
        const float* vpB = g_vals + rB*MAXNZ;
        float2 aA0 = {0.f,0.f}, aA1 = {0.f,0.f};
        float2 aB0 = {0.f,0.f}, aB1 = {0.f,0.f};
        #pragma unroll 1
        for (int k = 0; k < kmax; k += 4) {
            const int4   cA = *(const int4*)(cpA + k);
            const float4 vA = *(const float4*)(vpA + k);
            const int4   cB = *(const int4*)(cpB + k);
            const float4 vB = *(const float4*)(vpB + k);
            const int   ca[4] = {cA.x, cA.y, cA.z, cA.w};
            const float va[4] = {vA.x, vA.y, vA.z, vA.w};
            const int   cb[4] = {cB.x, cB.y, cB.z, cB.w};
            const float vb[4] = {vB.x, vB.y, vB.z, vB.w};
            #pragma unroll
            for (int u = 0; u < 4; u++) {
                const float2 p = hA2[ca[u]*32 + lane];
                aA0.x += va[u]*p.x; aA0.y += va[u]*p.y;
                const float2 r = hA2[cb[u]*32 + lane];
                aB0.x += vb[u]*r.x; aB0.y += vb[u]*r.y;
                if (NSRC == 2) {
                    const float2 q = hB2[ca[u]*32 + lane];
                    aA1.x += va[u]*q.x; aA1.y += va[u]*q.y;
                    const float2 s = hB2[cb[u]*32 + lane];
                    aB1.x += vb[u]*s.x; aB1.y += vb[u]*s.y;
                }
            }
        }
        store_hilo(s_src,          s_src + HALF,   warp*72 + 2*lane, aA0);
        store_hilo(s_src,          s_src + HALF,   (warp+16)*72 + 2*lane, aB0);
        if (NSRC == 2) {
            store_hilo(s_src + 4*HALF, s_src + 5*HALF, warp*72 + 2*lane, aA1);
            store_hilo(s_src + 4*HALF, s_src + 5*HALF, (warp+16)*72 + 2*lane, aB1);
        }
    }
    __syncthreads();

    // ---- tensor-core GEMM over NCH chunks (2-deep cp.async ring) ----
    const int g = lane >> 2, tig = lane & 3;
    const int mt = warp >> 3, ng = warp & 7;
    float acc[4][4];
    #pragma unroll
    for (int nt = 0; nt < 4; nt++) {
        const int col = (ng*4 + nt)*8 + 2*tig;
        const float b0v = btot[col], b1v = btot[col+1];
        acc[nt][0] = b0v; acc[nt][1] = b1v; acc[nt][2] = b0v; acc[nt][3] = b1v;
    }

    #pragma unroll 1
    for (int c = 0; c < NCH; c++) {
        if (c + 1 == NCH) cp_wait<0>(); else cp_wait<1>();
        __syncthreads();                          // chunk c resident
        const int slot = c >> 2, ks = c & 3;
        const __nv_bfloat16* ah = s_src + (slot*2+0)*HALF;
        const __nv_bfloat16* al = s_src + (slot*2+1)*HALF;
        unsigned Ah[4], Al[4];
        const int ab = (mt*16 + g)*72 + ks*16 + 2*tig;
        Ah[0] = *(const unsigned*)(ah + ab);
        Ah[1] = *(const unsigned*)(ah + ab + 8*72);
        Ah[2] = *(const unsigned*)(ah + ab + 8);
        Ah[3] = *(const unsigned*)(ah + ab + 8*72 + 8);
        Al[0] = *(const unsigned*)(al + ab);
        Al[1] = *(const unsigned*)(al + ab + 8*72);
        Al[2] = *(const unsigned*)(al + ab + 8);
        Al[3] = *(const unsigned*)(al + ab + 8*72 + 8);
        const unsigned* wp = s_w + (c & 1)*4096 + ng*512 + lane;
        #pragma unroll
        for (int nt = 0; nt < 4; nt++) {
            const unsigned b0h = wp[nt*128];
            const unsigned b1h = wp[nt*128 + 64];
            const unsigned b0l = wp[nt*128 + 32];
            const unsigned b1l = wp[nt*128 + 96];
            MMA_BF16(acc[nt], Ah, b0h, b1h);
            MMA_BF16(acc[nt], Ah, b0l, b1l);
            MMA_BF16(acc[nt], Al, b0h, b1h);
        }
        __syncthreads();                          // chunk c reads done
        if (c + 2 < NCH) issue_chunk(c + 2);
    }

    if (LAYER == 0) {   // rank-2 x terms: (A x_t)@gcWi0 + x_t@liWi0
        const int rA = r0 + mt*16 + g, rB = rA + 8;
        float sA[4], sB[4];
        sA[0] = g_AX  [rA*96 + 2*t]; sA[1] = g_AX  [rA*96 + 2*t + 1];
        sA[2] = g_Xall[rA*96 + 2*t]; sA[3] = g_Xall[rA*96 + 2*t + 1];
        sB[0] = g_AX  [rB*96 + 2*t]; sB[1] = g_AX  [rB*96 + 2*t + 1];
        sB[2] = g_Xall[rB*96 + 2*t]; sB[3] = g_Xall[rB*96 + 2*t + 1];
        #pragma unroll
        for (int nt = 0; nt < 4; nt++) {
            const int col = (ng*4 + nt)*8 + 2*tig;
            #pragma unroll
            for (int jx = 0; jx < 4; jx++) {
                const float w0 = g_WX[jx*256 + col], w1 = g_WX[jx*256 + col + 1];
                acc[nt][0] += sA[jx]*w0; acc[nt][1] += sA[jx]*w1;
                acc[nt][2] += sB[jx]*w0; acc[nt][3] += sB[jx]*w1;
            }
        }
    }

    // ---- comb -> smem, gates ----
    #pragma unroll
    for (int nt = 0; nt < 4; nt++) {
        const int col = (ng*4 + nt)*8 + 2*tig;
        *(float2*)(s_comb + (mt*16 + g)*256 + col)     = make_float2(acc[nt][0], acc[nt][1]);
        *(float2*)(s_comb + (mt*16 + g + 8)*256 + col) = make_float2(acc[nt][2], acc[nt][3]);
    }
    __syncthreads();
    for (int i = tid; i < RPB*64; i += 512) {
        const int n = i >> 6, hc = i & 63;
        const float ig = s_comb[n*256 + hc];
        const float fg = s_comb[n*256 + 64  + hc];
        const float og = s_comb[n*256 + 128 + hc];
        const float gg = s_comb[n*256 + 192 + hc];
        const int gi = (r0 + n)*64 + hc;
        const float cold = cst[gi];
        const float cnew = sigf(fg)*cold + sigf(ig)*tanhf(gg);
        cst[gi]  = cnew;
        hout[gi] = sigf(og)*tanhf(cnew);
    }
}

// out[n,p] = h1_final[n,:] @ outW + outb
__global__ void outproj_kernel(const float* __restrict__ outW,
                               const float* __restrict__ outb,
                               float* __restrict__ out) {
    const int idx = blockIdx.x*blockDim.x + threadIdx.x;
    if (idx >= NN*12) return;
    const int n = idx / 12, p = idx - n*12;
    const float* h = g_h1 + n*64;    // final ping index 0 after t=47
    float s = outb[p];
    #pragma unroll
    for (int k = 0; k < 64; k++) s += h[k] * outW[k*12 + p];
    out[idx] = s;
}

// ---------------- launch ----------------
extern "C" void kernel_launch(void* const* d_in, const int* in_sizes, int n_in,
                              void* d_out, int out_size) {
    (void)in_sizes; (void)n_in; (void)out_size;
    const float* x     = (const float*)d_in[0];
    const float* adj   = (const float*)d_in[1];
    const float* gcWi0 = (const float*)d_in[2];
    const float* gcbi0 = (const float*)d_in[3];
    const float* gcWh0 = (const float*)d_in[4];
    const float* gcbh0 = (const float*)d_in[5];
    const float* liWi0 = (const float*)d_in[6];
    const float* libi0 = (const float*)d_in[7];
    const float* liWh0 = (const float*)d_in[8];
    const float* libh0 = (const float*)d_in[9];
    const float* gcWi1 = (const float*)d_in[10];
    const float* gcbi1 = (const float*)d_in[11];
    const float* gcWh1 = (const float*)d_in[12];
    const float* gcbh1 = (const float*)d_in[13];
    const float* liWi1 = (const float*)d_in[14];
    const float* libi1 = (const float*)d_in[15];
    const float* liWh1 = (const float*)d_in[16];
    const float* libh1 = (const float*)d_in[17];
    const float* outW  = (const float*)d_in[18];
    const float* outb  = (const float*)d_in[19];
    float* out = (float*)d_out;

    const int SMEM = 36864 + 32768 + 32768;   // 102400
    cudaFuncSetAttribute(cell_kernel<0>, cudaFuncAttributeMaxDynamicSharedMemorySize, SMEM);
    cudaFuncSetAttribute(cell_kernel<1>, cudaFuncAttributeMaxDynamicSharedMemorySize, SMEM);

    // 5 setup launches, so ncu (-s 5 -c 1) profiles the first cell_kernel<0>.
    deg_kernel      <<<NN, 256>>>(adj);
    ell_kernel      <<<NN/8, 256>>>(adj);
    xallzero_kernel <<<(NN*96)/256, 256>>>(x);
    spmm96_kernel   <<<NN/8, 256>>>();
    wfragbias_kernel<<<384, 256>>>(gcWh0, liWh0, gcWi1, liWi1, gcWh1, liWh1,
                                   gcWi0, liWi0,
                                   gcbi0, gcbh0, libi0, libh0,
                                   gcbi1, gcbh1, libi1, libh1);

    for (int t = 0; t < TT; t++) {
        const int pi = t & 1;
        cell_kernel<0><<<GRID, 512, SMEM>>>(pi, t);
        cell_kernel<1><<<GRID, 512, SMEM>>>(pi, t);
    }
    outproj_kernel<<<(NN*12 + 255)/256, 256>>>(outW, outb, out);
}

// round 10
// speedup vs baseline: 1.6896x; 1.2301x over previous
#include <cuda_runtime.h>
#include <cuda_bf16.h>
#include <math.h>

#define NN 4096
#define TT 48
#define MAXNZ 128
#define SZH (NN*64)
#define RPB 32          // rows per block
#define GRID (NN/RPB)   // 128

// ---------------- device scratch (static, no allocation) ----------------
__device__ float g_dinv[NN];
__device__ int   g_cnt[NN];
__device__ int   g_cols[NN*MAXNZ];   // zero beyond cnt -> safe padded reads
__device__ float g_vals[NN*MAXNZ];   // zero beyond cnt -> products vanish
__device__ float g_Xall[NN*96];
__device__ float g_AX[NN*96];
__device__ float g_h0[2*SZH];        // h0(t) lives in buffer t&1
__device__ float g_h1[2*SZH];        // h1(t) lives in buffer t&1
__device__ float g_c0[SZH];
__device__ float g_c1[SZH];
__device__ float g_b0[256];
__device__ float g_b1[256];
__device__ float g_WX[4*256];                    // [gcWi0 r0,r1 ; liWi0 r0,r1]
__device__ __align__(16) unsigned g_Wf0[32768];  // layer0 W frags (K=128, 8 chunks)
__device__ __align__(16) unsigned g_Wf1[65536];  // layer1 W frags (K=256, 16 chunks)

__device__ __forceinline__ float sigf(float x) { return 1.0f / (1.0f + expf(-x)); }

// bf16 mma: D += A(16x16) * B(16x8), fp32 accum
#define MMA_BF16(C, A, b0, b1) \
    asm volatile("mma.sync.aligned.m16n8k16.row.col.f32.bf16.bf16.f32 " \
        "{%0,%1,%2,%3}, {%4,%5,%6,%7}, {%8,%9}, {%0,%1,%2,%3};" \
        : "+f"(C[0]), "+f"(C[1]), "+f"(C[2]), "+f"(C[3]) \
        : "r"(A[0]), "r"(A[1]), "r"(A[2]), "r"(A[3]), "r"(b0), "r"(b1))

__device__ __forceinline__ void cp_async16(void* s, const void* g) {
    unsigned sa = (unsigned)__cvta_generic_to_shared(s);
    asm volatile("cp.async.ca.shared.global [%0], [%1], 16;" :: "r"(sa), "l"(g));
}
__device__ __forceinline__ void cp_commit() {
    asm volatile("cp.async.commit_group;");
}
template<int Nq> __device__ __forceinline__ void cp_wait() {
    asm volatile("cp.async.wait_group %0;" :: "n"(Nq));
}

// pack float2 -> bf16 hi-pair + lo-pair (residual), store as u32 each
__device__ __forceinline__ void store_hilo(__nv_bfloat16* bhi, __nv_bfloat16* blo,
                                           int off, float2 v) {
    const __nv_bfloat16 hx = __float2bfloat16(v.x), hy = __float2bfloat16(v.y);
    const float rx = v.x - __bfloat162float(hx);
    const float ry = v.y - __bfloat162float(hy);
    const unsigned uh = (unsigned)__bfloat16_as_ushort(hx)
                      | ((unsigned)__bfloat16_as_ushort(hy) << 16);
    const unsigned ul = (unsigned)__bfloat16_as_ushort(__float2bfloat16(rx))
                      | ((unsigned)__bfloat16_as_ushort(__float2bfloat16(ry)) << 16);
    *(unsigned*)(bhi + off) = uh;
    *(unsigned*)(blo + off) = ul;
}

// ---------------- setup kernels ----------------

__global__ void deg_kernel(const float* __restrict__ adj) {
    __shared__ float red[256];
    const int r = blockIdx.x;
    float s = 0.0f;
    for (int c = threadIdx.x; c < NN; c += 256) s += adj[(long)r*NN + c];
    red[threadIdx.x] = s;
    __syncthreads();
    for (int o = 128; o > 0; o >>= 1) {
        if (threadIdx.x < o) red[threadIdx.x] += red[threadIdx.x + o];
        __syncthreads();
    }
    if (threadIdx.x == 0) g_dinv[r] = 1.0f / sqrtf(red[0] + 1.0f);
}

__global__ void ell_kernel(const float* __restrict__ adj) {
    const int lane = threadIdx.x & 31;
    const int r = blockIdx.x * 8 + (threadIdx.x >> 5);
    const float dr = g_dinv[r];
    int base = 0;
    for (int c0 = 0; c0 < NN; c0 += 32) {
        const int c = c0 + lane;
        float a = adj[(long)r*NN + c];
        if (c == r) a += 1.0f;
        const unsigned m = __ballot_sync(0xffffffffu, a != 0.0f);
        if (a != 0.0f) {
            const int pos = base + __popc(m & ((1u << lane) - 1u));
            if (pos < MAXNZ) {
                g_cols[r*MAXNZ + pos] = c;
                g_vals[r*MAXNZ + pos] = a * dr * g_dinv[c];
            }
        }
        base += __popc(m);
    }
    if (lane == 0) g_cnt[r] = (base < MAXNZ) ? base : MAXNZ;
}

// merged: Xall transpose + state zero + biases + WX copy (block 0)
__global__ void xallzero_kernel(
    const float* __restrict__ x,
    const float* __restrict__ gcWi0, const float* __restrict__ liWi0,
    const float* __restrict__ gcbi0, const float* __restrict__ gcbh0,
    const float* __restrict__ libi0, const float* __restrict__ libh0,
    const float* __restrict__ gcbi1, const float* __restrict__ gcbh1,
    const float* __restrict__ libi1, const float* __restrict__ libh1)
{
    const int idx = blockIdx.x * 256 + threadIdx.x;   // < NN*96
    const int n = idx / 96;
    const int q = idx - n * 96;
    const int t = q >> 1, i = q & 1;
    g_Xall[idx] = x[t * (NN*2) + n*2 + i];
    if (idx < SZH) {
        g_h0[idx] = 0.f; g_h0[SZH + idx] = 0.f;
        g_h1[idx] = 0.f; g_h1[SZH + idx] = 0.f;
        g_c0[idx] = 0.f; g_c1[idx] = 0.f;
    }
    if (blockIdx.x == 0) {
        const int c = threadIdx.x;
        g_b0[c] = gcbi0[c] + gcbh0[c] + libi0[c] + libh0[c];
        g_b1[c] = gcbi1[c] + gcbh1[c] + libi1[c] + libh1[c];
        g_WX[c]       = gcWi0[c];
        g_WX[256 + c] = gcWi0[256 + c];
        g_WX[512 + c] = liWi0[c];
        g_WX[768 + c] = liWi0[256 + c];
    }
}

// AX = A @ Xall (one warp/row) + cell0 seed at t=0 (h=c=0 -> comb = x-terms+bias)
__global__ void spmm96_kernel() {
    const int lane = threadIdx.x & 31;
    const int r = blockIdx.x * 8 + (threadIdx.x >> 5);
    const int cn = (g_cnt[r] + 3) & ~3;
    const int*   cp = g_cols + r*MAXNZ;
    const float* vp = g_vals + r*MAXNZ;
    float a0 = 0.f, a1 = 0.f, a2 = 0.f;
    #pragma unroll 1
    for (int k = 0; k < cn; k += 4) {
        const int4   c4 = *(const int4*)(cp + k);
        const float4 v4 = *(const float4*)(vp + k);
        const int   cc[4] = {c4.x, c4.y, c4.z, c4.w};
        const float vv[4] = {v4.x, v4.y, v4.z, v4.w};
        #pragma unroll
        for (int u = 0; u < 4; u++) {
            a0 += vv[u] * g_Xall[cc[u]*96 + lane];
            a1 += vv[u] * g_Xall[cc[u]*96 + lane + 32];
            a2 += vv[u] * g_Xall[cc[u]*96 + lane + 64];
        }
    }
    g_AX[r*96 + lane]      = a0;
    g_AX[r*96 + lane + 32] = a1;
    g_AX[r*96 + lane + 64] = a2;

    // ---- cell0(0) seed: h0(0) -> buf 0, c0 ----
    const float s0 = __shfl_sync(0xffffffffu, a0, 0);   // AX[r][0]
    const float s1 = __shfl_sync(0xffffffffu, a0, 1);   // AX[r][1]
    const float s2 = g_Xall[r*96 + 0];
    const float s3 = g_Xall[r*96 + 1];
    #pragma unroll
    for (int e = 0; e < 2; e++) {
        const int hc = 2*lane + e;
        float gv[4];
        #pragma unroll
        for (int qg = 0; qg < 4; qg++) {
            const int col = qg*64 + hc;
            gv[qg] = g_b0[col] + s0*g_WX[col] + s1*g_WX[256+col]
                   + s2*g_WX[512+col] + s3*g_WX[768+col];
        }
        const float cnew = sigf(gv[0])*tanhf(gv[3]);    // c_old = 0
        g_c0[r*64 + hc] = cnew;
        g_h0[r*64 + hc] = sigf(gv[2])*tanhf(cnew);      // buffer 0 = h0(0)
    }
}

// W fragment build
// frag layout within layer: (((ks*32 + nt)*2 + b)*2 + hl)*32 + lane
// k = ks*16 + b*8 + 2*tig (+1), n = nt*8 + g  (lane = g*4 + tig)
__global__ void wfrag_kernel(
    const float* __restrict__ gcWh0, const float* __restrict__ liWh0,
    const float* __restrict__ gcWi1, const float* __restrict__ liWi1,
    const float* __restrict__ gcWh1, const float* __restrict__ liWh1)
{
    const int idx = blockIdx.x * 256 + threadIdx.x;    // < 98304
    if (idx >= 98304) return;
    const int L = (idx >= 32768);
    const int j = L ? idx - 32768 : idx;
    const int lane = j & 31, hl = (j >> 5) & 1, b = (j >> 6) & 1;
    const int nt = (j >> 7) & 31, ks = j >> 12;
    const int g = lane >> 2, tig = lane & 3;
    const int k0 = ks*16 + b*8 + 2*tig;
    const int n  = nt*8 + g;
    unsigned short h2[2];
    #pragma unroll
    for (int e = 0; e < 2; e++) {
        const int k = k0 + e;
        const float* src;
        if (!L) src = (k < 64) ? (gcWh0 + k*256) : (liWh0 + (k-64)*256);
        else {
            const int q = k >> 6;
            src = (q == 0) ? (gcWi1 + k*256)
                : (q == 1) ? (liWi1 + (k-64)*256)
                : (q == 2) ? (gcWh1 + (k-128)*256)
                           : (liWh1 + (k-192)*256);
        }
        const float w = src[n];
        __nv_bfloat16 bh = __float2bfloat16(w);
        if (hl) bh = __float2bfloat16(w - __bfloat162float(bh));
        h2[e] = __bfloat16_as_ushort(bh);
    }
    const unsigned val = (unsigned)h2[0] | ((unsigned)h2[1] << 16);
    if (L) g_Wf1[j] = val; else g_Wf0[j] = val;
}

// ---------------- fused step kernel F(t): cell1(t) + cell0(t+1) ----------------
// Both consume only h0(t), h1(t-1) -> one launch, ONE gather of A@h0(t) serves
// both layers. smem: s_src 4 slots x 2 halves x (32*72) bf16 = 36864 B,
// s_w ring 2x16KB, s_comb 32x256 f32. Slots: 0=A@h0, 1=h0, 2=A@h1, 3=h1.
// W ring runs 24 chunks unbroken: c<16 -> Wf1/acc1 (slot c>>2), else Wf0/acc0
// (slot (c-16)>>2). t==47 stops at 16 chunks (no cell0(48); also avoids OOB
// x-term reads at t+1=48).
__global__ void __launch_bounds__(512, 1) fused_kernel(int t)
{
    constexpr int HALF = RPB * 72;
    extern __shared__ char smem[];
    __nv_bfloat16* s_src = (__nv_bfloat16*)smem;
    unsigned*      s_w   = (unsigned*)(smem + 36864);
    float*         s_comb= (float*)(smem + 36864 + 32768);

    const int pi = t & 1, pim = pi ^ 1;
    const float2* __restrict__ hA2 = (const float2*)(g_h0 + pi*SZH);   // h0(t)
    const float2* __restrict__ hB2 = (const float2*)(g_h1 + pim*SZH);  // h1(t-1)
    float* __restrict__ h1out = g_h1 + pi*SZH;                         // h1(t)
    float* __restrict__ h0out = g_h0 + pim*SZH;                        // h0(t+1)
    const bool do0 = (t < TT - 1);
    const int NCH = do0 ? 24 : 16;

    const int tid = threadIdx.x, lane = tid & 31, warp = tid >> 5;
    const int r0 = blockIdx.x * RPB;

    auto issue_chunk = [&](int c) {
        const unsigned* w = (c < 16) ? (g_Wf1 + c*4096) : (g_Wf0 + (c-16)*4096);
        const float4* gsrc = (const float4*)w;
        float4* dst = (float4*)(s_w + (c & 1)*4096);
        cp_async16(dst + tid,       gsrc + tid);
        cp_async16(dst + tid + 512, gsrc + tid + 512);
        cp_commit();
    };
    issue_chunk(0);
    issue_chunk(1);

    // ---- stage h0 -> slot1, h1 -> slot3 (own rows) ----
    for (int i = tid; i < RPB*32; i += 512) {
        const int n = i >> 5, l2 = i & 31;
        store_hilo(s_src + 2*HALF, s_src + 3*HALF, n*72 + 2*l2,
                   hA2[(r0+n)*32 + l2]);
        store_hilo(s_src + 6*HALF, s_src + 7*HALF, n*72 + 2*l2,
                   hB2[(r0+n)*32 + l2]);
    }

    // ---- SpMM gather: A@h0 -> slot0, A@h1 -> slot2 (2 rows/warp interleaved) ----
    {
        const int rA = r0 + warp, rB = r0 + warp + 16;
        const int cnA = (g_cnt[rA] + 3) & ~3;
        const int cnB = (g_cnt[rB] + 3) & ~3;
        const int kmax = cnA > cnB ? cnA : cnB;
        const int*   cpA = g_cols + rA*MAXNZ;
        const float* vpA = g_vals + rA*MAXNZ;
        const int*   cpB = g_cols + rB*MAXNZ;
        const float* vpB = g_vals + rB*MAXNZ;
        float2 aA0 = {0.f,0.f}, aA1 = {0.f,0.f};
        float2 aB0 = {0.f,0.f}, aB1 = {0.f,0.f};
        #pragma unroll 1
        for (int k = 0; k < kmax; k += 4) {
            const int4   cA = *(const int4*)(cpA + k);
            const float4 vA = *(const float4*)(vpA + k);
            const int4   cB = *(const int4*)(cpB + k);
            const float4 vB = *(const float4*)(vpB + k);
            const int   ca[4] = {cA.x, cA.y, cA.z, cA.w};
            const float va[4] = {vA.x, vA.y, vA.z, vA.w};
            const int   cb[4] = {cB.x, cB.y, cB.z, cB.w};
            const float vb[4] = {vB.x, vB.y, vB.z, vB.w};
            #pragma unroll
            for (int u = 0; u < 4; u++) {
                const float2 p = hA2[ca[u]*32 + lane];
                aA0.x += va[u]*p.x; aA0.y += va[u]*p.y;
                const float2 r = hA2[cb[u]*32 + lane];
                aB0.x += vb[u]*r.x; aB0.y += vb[u]*r.y;
                const float2 q = hB2[ca[u]*32 + lane];
                aA1.x += va[u]*q.x; aA1.y += va[u]*q.y;
                const float2 s = hB2[cb[u]*32 + lane];
                aB1.x += vb[u]*s.x; aB1.y += vb[u]*s.y;
            }
        }
        store_hilo(s_src,          s_src + HALF,   warp*72 + 2*lane, aA0);
        store_hilo(s_src,          s_src + HALF,   (warp+16)*72 + 2*lane, aB0);
        store_hilo(s_src + 4*HALF, s_src + 5*HALF, warp*72 + 2*lane, aA1);
        store_hilo(s_src + 4*HALF, s_src + 5*HALF, (warp+16)*72 + 2*lane, aB1);
    }
    __syncthreads();

    // ---- tensor-core GEMM over NCH chunks (2-deep cp.async ring) ----
    const int g = lane >> 2, tig = lane & 3;
    const int mt = warp >> 3, ng = warp & 7;
    float acc1[4][4], acc0[4][4];
    #pragma unroll
    for (int nt = 0; nt < 4; nt++) {
        const int col = (ng*4 + nt)*8 + 2*tig;
        acc1[nt][0] = g_b1[col]; acc1[nt][1] = g_b1[col+1];
        acc1[nt][2] = acc1[nt][0]; acc1[nt][3] = acc1[nt][1];
        acc0[nt][0] = g_b0[col]; acc0[nt][1] = g_b0[col+1];
        acc0[nt][2] = acc0[nt][0]; acc0[nt][3] = acc0[nt][1];
    }

    #pragma unroll 1
    for (int c = 0; c < NCH; c++) {
        if (c + 1 == NCH) cp_wait<0>(); else cp_wait<1>();
        __syncthreads();                          // chunk c resident
        const int cc = (c < 16) ? c : c - 16;
        const int slot = cc >> 2, ks = c & 3;
        const __nv_bfloat16* ah = s_src + (slot*2+0)*HALF;
        const __nv_bfloat16* al = s_src + (slot*2+1)*HALF;
        unsigned Ah[4], Al[4];
        const int ab = (mt*16 + g)*72 + ks*16 + 2*tig;
        Ah[0] = *(const unsigned*)(ah + ab);
        Ah[1] = *(const unsigned*)(ah + ab + 8*72);
        Ah[2] = *(const unsigned*)(ah + ab + 8);
        Ah[3] = *(const unsigned*)(ah + ab + 8*72 + 8);
        Al[0] = *(const unsigned*)(al + ab);
        Al[1] = *(const unsigned*)(al + ab + 8*72);
        Al[2] = *(const unsigned*)(al + ab + 8);
        Al[3] = *(const unsigned*)(al + ab + 8*72 + 8);
        const unsigned* wp = s_w + (c & 1)*4096 + ng*512 + lane;
        if (c < 16) {
            #pragma unroll
            for (int nt = 0; nt < 4; nt++) {
                const unsigned b0h = wp[nt*128];
                const unsigned b1h = wp[nt*128 + 64];
                const unsigned b0l = wp[nt*128 + 32];
                const unsigned b1l = wp[nt*128 + 96];
                MMA_BF16(acc1[nt], Ah, b0h, b1h);
                MMA_BF16(acc1[nt], Ah, b0l, b1l);
                MMA_BF16(acc1[nt], Al, b0h, b1h);
            }
        } else {
            #pragma unroll
            for (int nt = 0; nt < 4; nt++) {
                const unsigned b0h = wp[nt*128];
                const unsigned b1h = wp[nt*128 + 64];
                const unsigned b0l = wp[nt*128 + 32];
                const unsigned b1l = wp[nt*128 + 96];
                MMA_BF16(acc0[nt], Ah, b0h, b1h);
                MMA_BF16(acc0[nt], Ah, b0l, b1l);
                MMA_BF16(acc0[nt], Al, b0h, b1h);
            }
        }
        __syncthreads();                          // chunk c reads done
        if (c + 2 < NCH) issue_chunk(c + 2);
    }

    // ---- cell1 epilogue: comb1 -> gates -> h1(t), c1 ----
    #pragma unroll
    for (int nt = 0; nt < 4; nt++) {
        const int col = (ng*4 + nt)*8 + 2*tig;
        *(float2*)(s_comb + (mt*16 + g)*256 + col)     = make_float2(acc1[nt][0], acc1[nt][1]);
        *(float2*)(s_comb + (mt*16 + g + 8)*256 + col) = make_float2(acc1[nt][2], acc1[nt][3]);
    }
    __syncthreads();
    for (int i = tid; i < RPB*64; i += 512) {
        const int n = i >> 6, hc = i & 63;
        const float ig = s_comb[n*256 + hc];
        const float fg = s_comb[n*256 + 64  + hc];
        const float og = s_comb[n*256 + 128 + hc];
        const float gg = s_comb[n*256 + 192 + hc];
        const int gi = (r0 + n)*64 + hc;
        const float cold = g_c1[gi];
        const float cnew = sigf(fg)*cold + sigf(ig)*tanhf(gg);
        g_c1[gi]  = cnew;
        h1out[gi] = sigf(og)*tanhf(cnew);
    }

    // ---- cell0 epilogue: x-terms(t+1) + comb0 -> gates -> h0(t+1), c0 ----
    if (do0) {
        const int tn = t + 1;
        {   // rank-2 x terms: (A x_{t+1})@gcWi0 + x_{t+1}@liWi0
            const int rA = r0 + mt*16 + g, rB = rA + 8;
            float sA[4], sB[4];
            sA[0] = g_AX  [rA*96 + 2*tn]; sA[1] = g_AX  [rA*96 + 2*tn + 1];
            sA[2] = g_Xall[rA*96 + 2*tn]; sA[3] = g_Xall[rA*96 + 2*tn + 1];
            sB[0] = g_AX  [rB*96 + 2*tn]; sB[1] = g_AX  [rB*96 + 2*tn + 1];
            sB[2] = g_Xall[rB*96 + 2*tn]; sB[3] = g_Xall[rB*96 + 2*tn + 1];
            #pragma unroll
            for (int nt = 0; nt < 4; nt++) {
                const int col = (ng*4 + nt)*8 + 2*tig;
                #pragma unroll
                for (int jx = 0; jx < 4; jx++) {
                    const float w0 = g_WX[jx*256 + col], w1 = g_WX[jx*256 + col + 1];
                    acc0[nt][0] += sA[jx]*w0; acc0[nt][1] += sA[jx]*w1;
                    acc0[nt][2] += sB[jx]*w0; acc0[nt][3] += sB[jx]*w1;
                }
            }
        }
        __syncthreads();    // cell1 gate reads of s_comb done
        #pragma unroll
        for (int nt = 0; nt < 4; nt++) {
            const int col = (ng*4 + nt)*8 + 2*tig;
            *(float2*)(s_comb + (mt*16 + g)*256 + col)     = make_float2(acc0[nt][0], acc0[nt][1]);
            *(float2*)(s_comb + (mt*16 + g + 8)*256 + col) = make_float2(acc0[nt][2], acc0[nt][3]);
        }
        __syncthreads();
        for (int i = tid; i < RPB*64; i += 512) {
            const int n = i >> 6, hc = i & 63;
            const float ig = s_comb[n*256 + hc];
            const float fg = s_comb[n*256 + 64  + hc];
            const float og = s_comb[n*256 + 128 + hc];
            const float gg = s_comb[n*256 + 192 + hc];
            const int gi = (r0 + n)*64 + hc;
            const float cold = g_c0[gi];
            const float cnew = sigf(fg)*cold + sigf(ig)*tanhf(gg);
            g_c0[gi]  = cnew;
            h0out[gi] = sigf(og)*tanhf(cnew);
        }
    }
}

// out[n,p] = h1(47)[n,:] @ outW + outb ; h1(47) lives in buffer 47&1 = 1
__global__ void outproj_kernel(const float* __restrict__ outW,
                               const float* __restrict__ outb,
                               float* __restrict__ out) {
    const int idx = blockIdx.x*blockDim.x + threadIdx.x;
    if (idx >= NN*12) return;
    const int n = idx / 12, p = idx - n*12;
    const float* h = g_h1 + SZH + n*64;
    float s = outb[p];
    #pragma unroll
    for (int k = 0; k < 64; k++) s += h[k] * outW[k*12 + p];
    out[idx] = s;
}

// ---------------- launch ----------------
extern "C" void kernel_launch(void* const* d_in, const int* in_sizes, int n_in,
                              void* d_out, int out_size) {
    (void)in_sizes; (void)n_in; (void)out_size;
    const float* x     = (const float*)d_in[0];
    const float* adj   = (const float*)d_in[1];
    const float* gcWi0 = (const float*)d_in[2];
    const float* gcbi0 = (const float*)d_in[3];
    const float* gcWh0 = (const float*)d_in[4];
    const float* gcbh0 = (const float*)d_in[5];
    const float* liWi0 = (const float*)d_in[6];
    const float* libi0 = (const float*)d_in[7];
    const float* liWh0 = (const float*)d_in[8];
    const float* libh0 = (const float*)d_in[9];
    const float* gcWi1 = (const float*)d_in[10];
    const float* gcbi1 = (const float*)d_in[11];
    const float* gcWh1 = (const float*)d_in[12];
    const float* gcbh1 = (const float*)d_in[13];
    const float* liWi1 = (const float*)d_in[14];
    const float* libi1 = (const float*)d_in[15];
    const float* liWh1 = (const float*)d_in[16];
    const float* libh1 = (const float*)d_in[17];
    const float* outW  = (const float*)d_in[18];
    const float* outb  = (const float*)d_in[19];
    float* out = (float*)d_out;

    const int SMEM = 36864 + 32768 + 32768;   // 102400
    cudaFuncSetAttribute(fused_kernel,
                         cudaFuncAttributeMaxDynamicSharedMemorySize, SMEM);

    // 5 setup launches -> ncu (-s 5 -c 1) profiles fused_kernel(t=0).
    deg_kernel     <<<NN, 256>>>(adj);
    ell_kernel     <<<NN/8, 256>>>(adj);
    xallzero_kernel<<<(NN*96)/256, 256>>>(x, gcWi0, liWi0,
                                          gcbi0, gcbh0, libi0, libh0,
                                          gcbi1, gcbh1, libi1, libh1);
    spmm96_kernel  <<<NN/8, 256>>>();
    wfrag_kernel   <<<384, 256>>>(gcWh0, liWh0, gcWi1, liWi1, gcWh1, liWh1);

    for (int t = 0; t < TT; t++)
        fused_kernel<<<GRID, 512, SMEM>>>(t);
    outproj_kernel<<<(NN*12 + 255)/256, 256>>>(outW, outb, out);
}

// round 12
// speedup vs baseline: 1.7132x; 1.0140x over previous
#include <cuda_runtime.h>
#include <cuda_bf16.h>
#include <math.h>

#define NN 4096
#define TT 48
#define MAXNZ 128
#define SZH (NN*64)
#define RPB 32          // rows per block
#define GRID (NN/RPB)   // 128

// ---------------- device scratch (static, no allocation) ----------------
__device__ float g_dinv[NN];
__device__ int   g_cnt[NN];
__device__ int   g_cols[NN*MAXNZ];   // zero beyond cnt -> safe padded reads
__device__ float g_vals[NN*MAXNZ];   // zero beyond cnt -> products vanish
__device__ float g_Xall[NN*96];
__device__ float g_AX[NN*96];
__device__ float g_h0[2*SZH];        // h0(t) lives in buffer t&1
__device__ float g_h1[2*SZH];        // h1(t) lives in buffer t&1
__device__ float g_c0[SZH];
__device__ float g_c1[SZH];
__device__ float g_b0[256];
__device__ float g_b1[256];
__device__ float g_WX[4*256];                    // [gcWi0 r0,r1 ; liWi0 r0,r1]
__device__ __align__(16) unsigned g_Wf0[32768];  // layer0 W frags (K=128, 8 chunks)
__device__ __align__(16) unsigned g_Wf1[65536];  // layer1 W frags (K=256, 16 chunks)

// fast, flag-independent gate math (MUFU ex2/rcp based; clamped, no inf-inf)
__device__ __forceinline__ float sigf(float x) {
    return __fdividef(1.0f, 1.0f + __expf(-x));
}
__device__ __forceinline__ float tanhfast(float x) {
    float x2 = fminf(fmaxf(2.0f*x, -30.0f), 30.0f);
    const float e = __expf(x2);
    return __fdividef(e - 1.0f, e + 1.0f);
}

// bf16 mma: D += A(16x16) * B(16x8), fp32 accum
#define MMA_BF16(C, A, b0, b1) \
    asm volatile("mma.sync.aligned.m16n8k16.row.col.f32.bf16.bf16.f32 " \
        "{%0,%1,%2,%3}, {%4,%5,%6,%7}, {%8,%9}, {%0,%1,%2,%3};" \
        : "+f"(C[0]), "+f"(C[1]), "+f"(C[2]), "+f"(C[3]) \
        : "r"(A[0]), "r"(A[1]), "r"(A[2]), "r"(A[3]), "r"(b0), "r"(b1))

__device__ __forceinline__ void cp_async16(void* s, const void* g) {
    unsigned sa = (unsigned)__cvta_generic_to_shared(s);
    asm volatile("cp.async.ca.shared.global [%0], [%1], 16;" :: "r"(sa), "l"(g));
}
__device__ __forceinline__ void cp_commit() {
    asm volatile("cp.async.commit_group;");
}
template<int Nq> __device__ __forceinline__ void cp_wait() {
    asm volatile("cp.async.wait_group %0;" :: "n"(Nq));
}

// pack float2 -> bf16 hi-pair + lo-pair (residual), store as u32 each
__device__ __forceinline__ void store_hilo(__nv_bfloat16* bhi, __nv_bfloat16* blo,
                                           int off, float2 v) {
    const __nv_bfloat16 hx = __float2bfloat16(v.x), hy = __float2bfloat16(v.y);
    const float rx = v.x - __bfloat162float(hx);
    const float ry = v.y - __bfloat162float(hy);
    const unsigned uh = (unsigned)__bfloat16_as_ushort(hx)
                      | ((unsigned)__bfloat16_as_ushort(hy) << 16);
    const unsigned ul = (unsigned)__bfloat16_as_ushort(__float2bfloat16(rx))
                      | ((unsigned)__bfloat16_as_ushort(__float2bfloat16(ry)) << 16);
    *(unsigned*)(bhi + off) = uh;
    *(unsigned*)(blo + off) = ul;
}

// ---------------- setup kernels ----------------

__global__ void deg_kernel(const float* __restrict__ adj) {
    __shared__ float red[256];
    const int r = blockIdx.x;
    float s = 0.0f;
    for (int c = threadIdx.x; c < NN; c += 256) s += adj[(long)r*NN + c];
    red[threadIdx.x] = s;
    __syncthreads();
    for (int o = 128; o > 0; o >>= 1) {
        if (threadIdx.x < o) red[threadIdx.x] += red[threadIdx.x + o];
        __syncthreads();
    }
    if (threadIdx.x == 0) g_dinv[r] = 1.0f / sqrtf(red[0] + 1.0f);
}

// merged setup: blocks [0,512) ELL build; [512,2048) Xall+zero(+bias at 512);
// [2048,2432) W fragments. All three parts independent (need only g_dinv).
__global__ void setup2_kernel(
    const float* __restrict__ adj, const float* __restrict__ x,
    const float* __restrict__ gcWh0, const float* __restrict__ liWh0,
    const float* __restrict__ gcWi1, const float* __restrict__ liWi1,
    const float* __restrict__ gcWh1, const float* __restrict__ liWh1,
    const float* __restrict__ gcWi0, const float* __restrict__ liWi0,
    const float* __restrict__ gcbi0, const float* __restrict__ gcbh0,
    const float* __restrict__ libi0, const float* __restrict__ libh0,
    const float* __restrict__ gcbi1, const float* __restrict__ gcbh1,
    const float* __restrict__ libi1, const float* __restrict__ libh1)
{
    const int bx = blockIdx.x;
    if (bx < 512) {
        // ---- ELL build (deterministic ballot/popc compaction) ----
        const int lane = threadIdx.x & 31;
        const int r = bx * 8 + (threadIdx.x >> 5);
        const float dr = g_dinv[r];
        int base = 0;
        for (int c0 = 0; c0 < NN; c0 += 32) {
            const int c = c0 + lane;
            float a = adj[(long)r*NN + c];
            if (c == r) a += 1.0f;
            const unsigned m = __ballot_sync(0xffffffffu, a != 0.0f);
            if (a != 0.0f) {
                const int pos = base + __popc(m & ((1u << lane) - 1u));
                if (pos < MAXNZ) {
                    g_cols[r*MAXNZ + pos] = c;
                    g_vals[r*MAXNZ + pos] = a * dr * g_dinv[c];
                }
            }
            base += __popc(m);
        }
        if (lane == 0) g_cnt[r] = (base < MAXNZ) ? base : MAXNZ;
    } else if (bx < 2048) {
        // ---- Xall transpose + state zero ----
        const int idx = (bx - 512) * 256 + threadIdx.x;   // < NN*96
        const int n = idx / 96;
        const int q = idx - n * 96;
        const int t = q >> 1, i = q & 1;
        g_Xall[idx] = x[t * (NN*2) + n*2 + i];
        if (idx < SZH) {
            g_h0[idx] = 0.f; g_h0[SZH + idx] = 0.f;
            g_h1[idx] = 0.f; g_h1[SZH + idx] = 0.f;
            g_c0[idx] = 0.f; g_c1[idx] = 0.f;
        }
        if (bx == 512) {
            const int c = threadIdx.x;
            g_b0[c] = gcbi0[c] + gcbh0[c] + libi0[c] + libh0[c];
            g_b1[c] = gcbi1[c] + gcbh1[c] + libi1[c] + libh1[c];
            g_WX[c]       = gcWi0[c];
            g_WX[256 + c] = gcWi0[256 + c];
            g_WX[512 + c] = liWi0[c];
            g_WX[768 + c] = liWi0[256 + c];
        }
    } else {
        // ---- W fragment build ----
        // layout within layer: (((ks*32 + nt)*2 + b)*2 + hl)*32 + lane
        // k = ks*16 + b*8 + 2*tig (+1), n = nt*8 + g  (lane = g*4 + tig)
        const int idx = (bx - 2048) * 256 + threadIdx.x;    // < 98304
        const int L = (idx >= 32768);
        const int j = L ? idx - 32768 : idx;
        const int lane = j & 31, hl = (j >> 5) & 1, b = (j >> 6) & 1;
        const int nt = (j >> 7) & 31, ks = j >> 12;
        const int g = lane >> 2, tig = lane & 3;
        const int k0 = ks*16 + b*8 + 2*tig;
        const int n  = nt*8 + g;
        unsigned short h2[2];
        #pragma unroll
        for (int e = 0; e < 2; e++) {
            const int k = k0 + e;
            const float* src;
            if (!L) src = (k < 64) ? (gcWh0 + k*256) : (liWh0 + (k-64)*256);
            else {
                const int q = k >> 6;
                src = (q == 0) ? (gcWi1 + k*256)
                    : (q == 1) ? (liWi1 + (k-64)*256)
                    : (q == 2) ? (gcWh1 + (k-128)*256)
                               : (liWh1 + (k-192)*256);
            }
            const float w = src[n];
            __nv_bfloat16 bh = __float2bfloat16(w);
            if (hl) bh = __float2bfloat16(w - __bfloat162float(bh));
            h2[e] = __bfloat16_as_ushort(bh);
        }
        const unsigned val = (unsigned)h2[0] | ((unsigned)h2[1] << 16);
        if (L) g_Wf1[j] = val; else g_Wf0[j] = val;
    }
}

// AX = A @ Xall (one warp/row) + cell0 seed at t=0 (h=c=0 -> comb = x-terms+bias)
__global__ void spmm96_kernel() {
    const int lane = threadIdx.x & 31;
    const int r = blockIdx.x * 8 + (threadIdx.x >> 5);
    const int cn = (g_cnt[r] + 3) & ~3;
    const int*   cp = g_cols + r*MAXNZ;
    const float* vp = g_vals + r*MAXNZ;
    float a0 = 0.f, a1 = 0.f, a2 = 0.f;
    #pragma unroll 1
    for (int k = 0; k < cn; k += 4) {
        const int4   c4 = *(const int4*)(cp + k);
        const float4 v4 = *(const float4*)(vp + k);
        const int   cc[4] = {c4.x, c4.y, c4.z, c4.w};
        const float vv[4] = {v4.x, v4.y, v4.z, v4.w};
        #pragma unroll
        for (int u = 0; u < 4; u++) {
            a0 += vv[u] * g_Xall[cc[u]*96 + lane];
            a1 += vv[u] * g_Xall[cc[u]*96 + lane + 32];
            a2 += vv[u] * g_Xall[cc[u]*96 + lane + 64];
        }
    }
    g_AX[r*96 + lane]      = a0;
    g_AX[r*96 + lane + 32] = a1;
    g_AX[r*96 + lane + 64] = a2;

    // ---- cell0(0) seed: h0(0) -> buf 0, c0 ----
    const float s0 = __shfl_sync(0xffffffffu, a0, 0);   // AX[r][0]
    const float s1 = __shfl_sync(0xffffffffu, a0, 1);   // AX[r][1]
    const float s2 = g_Xall[r*96 + 0];
    const float s3 = g_Xall[r*96 + 1];
    #pragma unroll
    for (int e = 0; e < 2; e++) {
        const int hc = 2*lane + e;
        float gv[4];
        #pragma unroll
        for (int qg = 0; qg < 4; qg++) {
            const int col = qg*64 + hc;
            gv[qg] = g_b0[col] + s0*g_WX[col] + s1*g_WX[256+col]
                   + s2*g_WX[512+col] + s3*g_WX[768+col];
        }
        const float cnew = sigf(gv[0])*tanhfast(gv[3]);    // c_old = 0
        g_c0[r*64 + hc] = cnew;
        g_h0[r*64 + hc] = sigf(gv[2])*tanhfast(cnew);      // buffer 0 = h0(0)
    }
}

// ---------------- fused step kernel F(t): cell1(t) + cell0(t+1) ----------------
// Both consume only h0(t), h1(t-1) -> one launch, ONE gather of A@h0(t) serves
// both layers. smem: s_src 4 slots x 2 halves x (32*72) bf16 = 36864 B,
// s_w ring 2x16KB, s_comb 32x256 f32. Slots: 0=A@h0, 1=h0, 2=A@h1, 3=h1.
// W ring runs 24 chunks unbroken: c<16 -> Wf1/acc1 (slot c>>2), else Wf0/acc0
// (slot (c-16)>>2). t==47 stops at 16 chunks.
__global__ void __launch_bounds__(512, 1) fused_kernel(int t)
{
    constexpr int HALF = RPB * 72;
    extern __shared__ char smem[];
    __nv_bfloat16* s_src = (__nv_bfloat16*)smem;
    unsigned*      s_w   = (unsigned*)(smem + 36864);
    float*         s_comb= (float*)(smem + 36864 + 32768);

    const int pi = t & 1, pim = pi ^ 1;
    const float2* __restrict__ hA2 = (const float2*)(g_h0 + pi*SZH);   // h0(t)
    const float2* __restrict__ hB2 = (const float2*)(g_h1 + pim*SZH);  // h1(t-1)
    float* __restrict__ h1out = g_h1 + pi*SZH;                         // h1(t)
    float* __restrict__ h0out = g_h0 + pim*SZH;                        // h0(t+1)
    const bool do0 = (t < TT - 1);
    const int NCH = do0 ? 24 : 16;

    const int tid = threadIdx.x, lane = tid & 31, warp = tid >> 5;
    const int r0 = blockIdx.x * RPB;

    auto issue_chunk = [&](int c) {
        const unsigned* w = (c < 16) ? (g_Wf1 + c*4096) : (g_Wf0 + (c-16)*4096);
        const float4* gsrc = (const float4*)w;
        float4* dst = (float4*)(s_w + (c & 1)*4096);
        cp_async16(dst + tid,       gsrc + tid);
        cp_async16(dst + tid + 512, gsrc + tid + 512);
        cp_commit();
    };
    issue_chunk(0);
    issue_chunk(1);

    // ---- stage h0 -> slot1, h1 -> slot3 (own rows) ----
    for (int i = tid; i < RPB*32; i += 512) {
        const int n = i >> 5, l2 = i & 31;
        store_hilo(s_src + 2*HALF, s_src + 3*HALF, n*72 + 2*l2,
                   hA2[(r0+n)*32 + l2]);
        store_hilo(s_src + 6*HALF, s_src + 7*HALF, n*72 + 2*l2,
                   hB2[(r0+n)*32 + l2]);
    }

    // ---- SpMM gather: A@h0 -> slot0, A@h1 -> slot2 (2 rows/warp interleaved) ----
    {
        const int rA = r0 + warp, rB = r0 + warp + 16;
        const int cnA = (g_cnt[rA] + 3) & ~3;
        const int cnB = (g_cnt[rB] + 3) & ~3;
        const int kmax = cnA > cnB ? cnA : cnB;
        const int*   cpA = g_cols + rA*MAXNZ;
        const float* vpA = g_vals + rA*MAXNZ;
        const int*   cpB = g_cols + rB*MAXNZ;
        const float* vpB = g_vals + rB*MAXNZ;
        float2 aA0 = {0.f,0.f}, aA1 = {0.f,0.f};
        float2 aB0 = {0.f,0.f}, aB1 = {0.f,0.f};
        #pragma unroll 1
        for (int k = 0; k < kmax; k += 4) {
            const int4   cA = *(const int4*)(cpA + k);
            const float4 vA = *(const float4*)(vpA + k);
            const int4   cB = *(const int4*)(cpB + k);
            const float4 vB = *(const float4*)(vpB + k);
            const int   ca[4] = {cA.x, cA.y, cA.z, cA.w};
            const float va[4] = {vA.x, vA.y, vA.z, vA.w};
            const int   cb[4] = {cB.x, cB.y, cB.z, cB.w};
            const float vb[4] = {vB.x, vB.y, vB.z, vB.w};
            #pragma unroll
            for (int u = 0; u < 4; u++) {
                const float2 p = hA2[ca[u]*32 + lane];
                aA0.x += va[u]*p.x; aA0.y += va[u]*p.y;
                const float2 r = hA2[cb[u]*32 + lane];
                aB0.x += vb[u]*r.x; aB0.y += vb[u]*r.y;
                const float2 q = hB2[ca[u]*32 + lane];
                aA1.x += va[u]*q.x; aA1.y += va[u]*q.y;
                const float2 s = hB2[cb[u]*32 + lane];
                aB1.x += vb[u]*s.x; aB1.y += vb[u]*s.y;
            }
        }
        store_hilo(s_src,          s_src + HALF,   warp*72 + 2*lane, aA0);
        store_hilo(s_src,          s_src + HALF,   (warp+16)*72 + 2*lane, aB0);
        store_hilo(s_src + 4*HALF, s_src + 5*HALF, warp*72 + 2*lane, aA1);
        store_hilo(s_src + 4*HALF, s_src + 5*HALF, (warp+16)*72 + 2*lane, aB1);
    }
    __syncthreads();

    // ---- tensor-core GEMM over NCH chunks (2-deep cp.async ring) ----
    const int g = lane >> 2, tig = lane & 3;
    const int mt = warp >> 3, ng = warp & 7;
    float acc1[4][4], acc0[4][4];
    #pragma unroll
    for (int nt = 0; nt < 4; nt++) {
        const int col = (ng*4 + nt)*8 + 2*tig;
        acc1[nt][0] = g_b1[col]; acc1[nt][1] = g_b1[col+1];
        acc1[nt][2] = acc1[nt][0]; acc1[nt][3] = acc1[nt][1];
        acc0[nt][0] = g_b0[col]; acc0[nt][1] = g_b0[col+1];
        acc0[nt][2] = acc0[nt][0]; acc0[nt][3] = acc0[nt][1];
    }

    #pragma unroll 1
    for (int c = 0; c < NCH; c++) {
        if (c + 1 == NCH) cp_wait<0>(); else cp_wait<1>();
        __syncthreads();                          // chunk c resident
        const int cc = (c < 16) ? c : c - 16;
        const int slot = cc >> 2, ks = c & 3;
        const __nv_bfloat16* ah = s_src + (slot*2+0)*HALF;
        const __nv_bfloat16* al = s_src + (slot*2+1)*HALF;
        unsigned Ah[4], Al[4];
        const int ab = (mt*16 + g)*72 + ks*16 + 2*tig;
        Ah[0] = *(const unsigned*)(ah + ab);
        Ah[1] = *(const unsigned*)(ah + ab + 8*72);
        Ah[2] = *(const unsigned*)(ah + ab + 8);
        Ah[3] = *(const unsigned*)(ah + ab + 8*72 + 8);
        Al[0] = *(const unsigned*)(al + ab);
        Al[1] = *(const unsigned*)(al + ab + 8*72);
        Al[2] = *(const unsigned*)(al + ab + 8);
        Al[3] = *(const unsigned*)(al + ab + 8*72 + 8);
        const unsigned* wp = s_w + (c & 1)*4096 + ng*512 + lane;
        if (c < 16) {
            #pragma unroll
            for (int nt = 0; nt < 4; nt++) {
                const unsigned b0h = wp[nt*128];
                const unsigned b1h = wp[nt*128 + 64];
                const unsigned b0l = wp[nt*128 + 32];
                const unsigned b1l = wp[nt*128 + 96];
                MMA_BF16(acc1[nt], Ah, b0h, b1h);
                MMA_BF16(acc1[nt], Ah, b0l, b1l);
                MMA_BF16(acc1[nt], Al, b0h, b1h);
            }
        } else {
            #pragma unroll
            for (int nt = 0; nt < 4; nt++) {
                const unsigned b0h = wp[nt*128];
                const unsigned b1h = wp[nt*128 + 64];
                const unsigned b0l = wp[nt*128 + 32];
                const unsigned b1l = wp[nt*128 + 96];
                MMA_BF16(acc0[nt], Ah, b0h, b1h);
                MMA_BF16(acc0[nt], Ah, b0l, b1l);
                MMA_BF16(acc0[nt], Al, b0h, b1h);
            }
        }
        __syncthreads();                          // chunk c reads done
        if (c + 2 < NCH) issue_chunk(c + 2);
    }

    // ---- cell1 epilogue: comb1 -> gates -> h1(t), c1 ----
    #pragma unroll
    for (int nt = 0; nt < 4; nt++) {
        const int col = (ng*4 + nt)*8 + 2*tig;
        *(float2*)(s_comb + (mt*16 + g)*256 + col)     = make_float2(acc1[nt][0], acc1[nt][1]);
        *(float2*)(s_comb + (mt*16 + g + 8)*256 + col) = make_float2(acc1[nt][2], acc1[nt][3]);
    }
    __syncthreads();
    for (int i = tid; i < RPB*64; i += 512) {
        const int n = i >> 6, hc = i & 63;
        const float ig = s_comb[n*256 + hc];
        const float fg = s_comb[n*256 + 64  + hc];
        const float og = s_comb[n*256 + 128 + hc];
        const float gg = s_comb[n*256 + 192 + hc];
        const int gi = (r0 + n)*64 + hc;
        const float cold = g_c1[gi];
        const float cnew = sigf(fg)*cold + sigf(ig)*tanhfast(gg);
        g_c1[gi]  = cnew;
        h1out[gi] = sigf(og)*tanhfast(cnew);
    }

    // ---- cell0 epilogue: x-terms(t+1) + comb0 -> gates -> h0(t+1), c0 ----
    if (do0) {
        const int tn = t + 1;
        {   // rank-2 x terms: (A x_{t+1})@gcWi0 + x_{t+1}@liWi0
            const int rA = r0 + mt*16 + g, rB = rA + 8;
            float sA[4], sB[4];
            sA[0] = g_AX  [rA*96 + 2*tn]; sA[1] = g_AX  [rA*96 + 2*tn + 1];
            sA[2] = g_Xall[rA*96 + 2*tn]; sA[3] = g_Xall[rA*96 + 2*tn + 1];
            sB[0] = g_AX  [rB*96 + 2*tn]; sB[1] = g_AX  [rB*96 + 2*tn + 1];
            sB[2] = g_Xall[rB*96 + 2*tn]; sB[3] = g_Xall[rB*96 + 2*tn + 1];
            #pragma unroll
            for (int nt = 0; nt < 4; nt++) {
                const int col = (ng*4 + nt)*8 + 2*tig;
                #pragma unroll
                for (int jx = 0; jx < 4; jx++) {
                    const float w0 = g_WX[jx*256 + col], w1 = g_WX[jx*256 + col + 1];
                    acc0[nt][0] += sA[jx]*w0; acc0[nt][1] += sA[jx]*w1;
                    acc0[nt][2] += sB[jx]*w0; acc0[nt][3] += sB[jx]*w1;
                }
            }
        }
        __syncthreads();    // cell1 gate reads of s_comb done
        #pragma unroll
        for (int nt = 0; nt < 4; nt++) {
            const int col = (ng*4 + nt)*8 + 2*tig;
            *(float2*)(s_comb + (mt*16 + g)*256 + col)     = make_float2(acc0[nt][0], acc0[nt][1]);
            *(float2*)(s_comb + (mt*16 + g + 8)*256 + col) = make_float2(acc0[nt][2], acc0[nt][3]);
        }
        __syncthreads();
        for (int i = tid; i < RPB*64; i += 512) {
            const int n = i >> 6, hc = i & 63;
            const float ig = s_comb[n*256 + hc];
            const float fg = s_comb[n*256 + 64  + hc];
            const float og = s_comb[n*256 + 128 + hc];
            const float gg = s_comb[n*256 + 192 + hc];
            const int gi = (r0 + n)*64 + hc;
            const float cold = g_c0[gi];
            const float cnew = sigf(fg)*cold + sigf(ig)*tanhfast(gg);
            g_c0[gi]  = cnew;
            h0out[gi] = sigf(og)*tanhfast(cnew);
        }
    }
}

// out[n,p] = h1(47)[n,:] @ outW + outb ; h1(47) lives in buffer 47&1 = 1
__global__ void outproj_kernel(const float* __restrict__ outW,
                               const float* __restrict__ outb,
                               float* __restrict__ out) {
    const int idx = blockIdx.x*blockDim.x + threadIdx.x;
    if (idx >= NN*12) return;
    const int n = idx / 12, p = idx - n*12;
    const float* h = g_h1 + SZH + n*64;
    float s = outb[p];
    #pragma unroll
    for (int k = 0; k < 64; k++) s += h[k] * outW[k*12 + p];
    out[idx] = s;
}

// ---------------- launch ----------------
extern "C" void kernel_launch(void* const* d_in, const int* in_sizes, int n_in,
                              void* d_out, int out_size) {
    (void)in_sizes; (void)n_in; (void)out_size;
    const float* x     = (const float*)d_in[0];
    const float* adj   = (const float*)d_in[1];
    const float* gcWi0 = (const float*)d_in[2];
    const float* gcbi0 = (const float*)d_in[3];
    const float* gcWh0 = (const float*)d_in[4];
    const float* gcbh0 = (const float*)d_in[5];
    const float* liWi0 = (const float*)d_in[6];
    const float* libi0 = (const float*)d_in[7];
    const float* liWh0 = (const float*)d_in[8];
    const float* libh0 = (const float*)d_in[9];
    const float* gcWi1 = (const float*)d_in[10];
    const float* gcbi1 = (const float*)d_in[11];
    const float* gcWh1 = (const float*)d_in[12];
    const float* gcbh1 = (const float*)d_in[13];
    const float* liWi1 = (const float*)d_in[14];
    const float* libi1 = (const float*)d_in[15];
    const float* liWh1 = (const float*)d_in[16];
    const float* libh1 = (const float*)d_in[17];
    const float* outW  = (const float*)d_in[18];
    const float* outb  = (const float*)d_in[19];
    float* out = (float*)d_out;

    const int SMEM = 36864 + 32768 + 32768;   // 102400
    cudaFuncSetAttribute(fused_kernel,
                         cudaFuncAttributeMaxDynamicSharedMemorySize, SMEM);

    // 3 setup launches -> fused_kernel(t=0) is the 4th launch (the one ncu
    // has been observed to profile).
    deg_kernel   <<<NN, 256>>>(adj);
    setup2_kernel<<<2432, 256>>>(adj, x,
                                 gcWh0, liWh0, gcWi1, liWi1, gcWh1, liWh1,
                                 gcWi0, liWi0,
                                 gcbi0, gcbh0, libi0, libh0,
                                 gcbi1, gcbh1, libi1, libh1);
    spmm96_kernel<<<NN/8, 256>>>();

    for (int t = 0; t < TT; t++)
        fused_kernel<<<GRID, 512, SMEM>>>(t);
    outproj_kernel<<<(NN*12 + 255)/256, 256>>>(outW, outb, out);
}